// round 6
// baseline (speedup 1.0000x reference)
#include <cuda_runtime.h>
#include <cuda_fp16.h>
#include <math.h>
#include <stdint.h>

// Problem constants
#define T_TOKENS 2048
#define HIDDEN   2048
#define INTER    5632
#define NEXP     8
#define TOPK     2
#define NPAIRS   (T_TOKENS * TOPK)   // 4096
#define CAP      2048

// ---------------- device scratch ----------------
__device__ int d_cnt[NEXP];
__device__ int d_list[NEXP * CAP];
__device__ int d_eid[NPAIRS];
__device__ float d_wgt[NPAIRS];

__device__ __align__(16) float d_G[(size_t)NPAIRS * INTER];   // gate, then act (in-place)
__device__ __align__(16) float d_U[(size_t)NPAIRS * INTER];   // up
__device__ __align__(16) float d_Y[(size_t)NPAIRS * HIDDEN];  // per-pair down output

// ---------------- small kernels ----------------
__global__ void init_kernel() {
    if (threadIdx.x < NEXP) d_cnt[threadIdx.x] = 0;
}

__global__ void router_kernel(const float* __restrict__ x, const float* __restrict__ wr) {
    int warp = threadIdx.x >> 5;
    int lane = threadIdx.x & 31;
    int t = blockIdx.x * 8 + warp;
    if (t >= T_TOKENS) return;

    float acc[NEXP];
#pragma unroll
    for (int e = 0; e < NEXP; e++) acc[e] = 0.f;
    const float* xr = x + (size_t)t * HIDDEN;
    for (int j = lane; j < HIDDEN; j += 32) {
        float xv = xr[j];
#pragma unroll
        for (int e = 0; e < NEXP; e++) acc[e] += xv * wr[e * HIDDEN + j];
    }
#pragma unroll
    for (int e = 0; e < NEXP; e++) {
#pragma unroll
        for (int off = 16; off; off >>= 1)
            acc[e] += __shfl_xor_sync(0xffffffffu, acc[e], off);
    }
    if (lane == 0) {
        int e0 = 0;
#pragma unroll
        for (int e = 1; e < NEXP; e++) if (acc[e] > acc[e0]) e0 = e;
        int e1 = -1;
#pragma unroll
        for (int e = 0; e < NEXP; e++) {
            if (e == e0) continue;
            if (e1 < 0 || acc[e] > acc[e1]) e1 = e;
        }
        float v0 = acc[e0], v1 = acc[e1];
        float w1 = 1.f / (1.f + expf(v0 - v1));
        float w0 = 1.f - w1;
        d_eid[2 * t] = e0;  d_eid[2 * t + 1] = e1;
        d_wgt[2 * t] = w0;  d_wgt[2 * t + 1] = w1;
    }
}

__global__ void compact_kernel() {
    int p = blockIdx.x * blockDim.x + threadIdx.x;
    if (p >= NPAIRS) return;
    int e = d_eid[p];
    int pos = atomicAdd(&d_cnt[e], 1);
    d_list[e * CAP + pos] = p;
}

// ---------------- helpers ----------------
__device__ __forceinline__ uint32_t smem_u32(const void* p) {
    uint32_t a;
    asm("{ .reg .u64 t; cvta.to.shared.u64 t, %1; cvt.u32.u64 %0, t; }" : "=r"(a) : "l"(p));
    return a;
}
__device__ __forceinline__ uint32_t packh2(float lo, float hi) {
    __half2 h = __floats2half2_rn(lo, hi);
    return *(uint32_t*)&h;
}
// split a float2 into hi-packed and lo-packed fp16x2
__device__ __forceinline__ void split2(float2 f, uint32_t& hi, uint32_t& lo) {
    __half2 h = __floats2half2_rn(f.x, f.y);
    hi = *(uint32_t*)&h;
    float2 fb = __half22float2(h);
    __half2 l = __floats2half2_rn(f.x - fb.x, f.y - fb.y);
    lo = *(uint32_t*)&l;
}
__device__ __forceinline__ void mma_f16(float* c, const uint32_t* a, const uint32_t* b) {
    asm volatile("mma.sync.aligned.m16n8k16.row.col.f32.f16.f16.f32 "
                 "{%0,%1,%2,%3}, {%4,%5,%6,%7}, {%8,%9}, {%0,%1,%2,%3};"
                 : "+f"(c[0]), "+f"(c[1]), "+f"(c[2]), "+f"(c[3])
                 : "r"(a[0]), "r"(a[1]), "r"(a[2]), "r"(a[3]),
                   "r"(b[0]), "r"(b[1]));
}
__device__ __forceinline__ void cp16(uint32_t smem_dst, const void* gptr) {
    asm volatile("cp.async.cg.shared.global [%0], [%1], 16;" :: "r"(smem_dst), "l"(gptr));
}

// ---------------- expert-grouped fp16-split tensor GEMM ----------------
// C[pid][n] = sum_k A[pid>>shift][k] * B_e[n][k]
// Tile: BM=128, BN=256, BK=32. 256 threads, 8 warps in 2(m) x 4(n), warp tile 64x64.
// Each logical tf32-precision MMA realized as 3 fp16 m16n8k16 MMAs (hi/lo split).
#define BK 32
#define SMS 36                                 // padded smem row stride (floats)
#define STAGE_F ((128 + 256) * SMS)            // floats per stage: A(128) + B(256) rows
#define NSTAGE 3

__global__ __launch_bounds__(256, 1)
void gemm_tc(const float* __restrict__ Aext, const float* __restrict__ Ball,
             int N, int K, int lda, int shift, int asel, int csel)
{
    int e = blockIdx.z;
    int n_e = d_cnt[e];
    int mbase = blockIdx.y * 128;
    if (mbase >= n_e) return;
    int nbase = blockIdx.x * 256;

    const float* A = asel ? d_G : Aext;
    float* C = (csel == 0) ? d_G : (csel == 1) ? d_U : d_Y;
    const float* B = Ball + (size_t)e * N * K;

    extern __shared__ float sm[];
    int* s_pid = (int*)(sm + NSTAGE * STAGE_F);
    uint32_t smbase = smem_u32(sm);

    int tid = threadIdx.x;
    int lane = tid & 31;
    int wid = tid >> 5;
    int wm = wid & 1;          // 0..1  (64 rows each)
    int wn = wid >> 1;         // 0..3  (64 cols each)

    if (tid < 128) {
        int lp = mbase + tid;
        s_pid[tid] = d_list[e * CAP + (lp < n_e ? lp : mbase)];
    }
    __syncthreads();

    // loader mapping: A 4 chunks/thread, B 8 chunks/thread; chunk = (row, 16B of k)
    const char* aG[4];
    const char* bG[8];
    uint32_t aS[4], bS[8];
#pragma unroll
    for (int i = 0; i < 4; i++) {
        int idx = tid + i * 256;          // 0..1023
        int row = idx >> 3;
        int c4  = (idx & 7) * 4;
        aG[i] = (const char*)(A + (size_t)(s_pid[row] >> shift) * lda + c4);
        aS[i] = (uint32_t)((row * SMS + c4) * 4);
    }
#pragma unroll
    for (int i = 0; i < 8; i++) {
        int idx = tid + i * 256;          // 0..2047
        int row = idx >> 3;
        int c4  = (idx & 7) * 4;
        bG[i] = (const char*)(B + (size_t)(nbase + row) * K + c4);
        bS[i] = (uint32_t)((128 * SMS + row * SMS + c4) * 4);
    }

    int KT = K / BK;

    auto issue = [&](int st, int kb) {
        uint32_t sb = smbase + (uint32_t)(st * STAGE_F * 4);
        size_t go = (size_t)kb * BK * 4;
#pragma unroll
        for (int i = 0; i < 4; i++) cp16(sb + aS[i], aG[i] + go);
#pragma unroll
        for (int i = 0; i < 8; i++) cp16(sb + bS[i], bG[i] + go);
        asm volatile("cp.async.commit_group;" ::: "memory");
    };

    issue(0, 0);
    issue(1, 1);

    float acc[4][8][4];
#pragma unroll
    for (int mt = 0; mt < 4; mt++)
#pragma unroll
        for (int nt = 0; nt < 8; nt++)
#pragma unroll
            for (int q = 0; q < 4; q++) acc[mt][nt][q] = 0.f;

    int arow = wm * 64 + (lane >> 2);
    int brow = wn * 64 + (lane >> 2);
    int kcol2 = (lane & 3) * 2;

    for (int kb = 0; kb < KT; kb++) {
        int st = kb % NSTAGE;
        if (kb + 2 < KT) {
            __syncthreads();                       // WAR: stage (kb+2)%3 fully consumed
            issue((kb + 2) % NSTAGE, kb + 2);
            asm volatile("cp.async.wait_group 2;" ::: "memory");
        } else if (kb + 1 < KT) {
            asm volatile("cp.async.wait_group 1;" ::: "memory");
        } else {
            asm volatile("cp.async.wait_group 0;" ::: "memory");
        }
        __syncthreads();                           // stage kb visible

        const float* cA = sm + st * STAGE_F;
        const float* cB = cA + 128 * SMS;
#pragma unroll
        for (int ks = 0; ks < 2; ks++) {           // two k16 steps per BK=32
            int kc = ks * 16 + kcol2;
            // ---- A fragments: hi and lo ----
            uint32_t ah[4][4], al[4][4];
#pragma unroll
            for (int mt = 0; mt < 4; mt++) {
                const float* p = cA + (arow + mt * 16) * SMS + kc;
                split2(*(const float2*)(p),              ah[mt][0], al[mt][0]);
                split2(*(const float2*)(p + 8 * SMS),    ah[mt][1], al[mt][1]);
                split2(*(const float2*)(p + 8),          ah[mt][2], al[mt][2]);
                split2(*(const float2*)(p + 8 * SMS + 8),ah[mt][3], al[mt][3]);
            }
            // ---- B hi fragments ----
            uint32_t bb[8][2];
            uint32_t bl[8][2];
#pragma unroll
            for (int nt = 0; nt < 8; nt++) {
                const float* p = cB + (brow + nt * 8) * SMS + kc;
                split2(*(const float2*)(p),     bb[nt][0], bl[nt][0]);
                split2(*(const float2*)(p + 8), bb[nt][1], bl[nt][1]);
            }
            // term 1: ah * bh
#pragma unroll
            for (int mt = 0; mt < 4; mt++)
#pragma unroll
                for (int nt = 0; nt < 8; nt++)
                    mma_f16(acc[mt][nt], ah[mt], bb[nt]);
            // term 2: al * bh
#pragma unroll
            for (int mt = 0; mt < 4; mt++)
#pragma unroll
                for (int nt = 0; nt < 8; nt++)
                    mma_f16(acc[mt][nt], al[mt], bb[nt]);
            // term 3: ah * bl
#pragma unroll
            for (int mt = 0; mt < 4; mt++)
#pragma unroll
                for (int nt = 0; nt < 8; nt++)
                    mma_f16(acc[mt][nt], ah[mt], bl[nt]);
        }
    }

    // ---- epilogue: scatter accum rows via pid list ----
    int gid = lane >> 2;      // 0..7
    int tig = lane & 3;       // 0..3
#pragma unroll
    for (int mt = 0; mt < 4; mt++) {
        int mrow0 = wm * 64 + mt * 16 + gid;
        int mrow1 = mrow0 + 8;
        bool v0 = (mbase + mrow0) < n_e;
        bool v1 = (mbase + mrow1) < n_e;
        float* c0 = v0 ? (C + (size_t)s_pid[mrow0] * N + nbase + wn * 64 + tig * 2) : (float*)0;
        float* c1 = v1 ? (C + (size_t)s_pid[mrow1] * N + nbase + wn * 64 + tig * 2) : (float*)0;
#pragma unroll
        for (int nt = 0; nt < 8; nt++) {
            if (v0) *(float2*)(c0 + nt * 8) = make_float2(acc[mt][nt][0], acc[mt][nt][1]);
            if (v1) *(float2*)(c1 + nt * 8) = make_float2(acc[mt][nt][2], acc[mt][nt][3]);
        }
    }
}

#define DYN_BYTES (NSTAGE * STAGE_F * 4 + 128 * 4 + 16)

// ---------------- elementwise ----------------
__global__ void act_kernel() {
    size_t i = (size_t)blockIdx.x * blockDim.x + threadIdx.x;
    if (i >= (size_t)NPAIRS * INTER / 4) return;
    float4 g = ((const float4*)d_G)[i];
    float4 u = ((const float4*)d_U)[i];
    float4 o;
    o.x = g.x / (1.f + expf(-g.x)) * u.x;
    o.y = g.y / (1.f + expf(-g.y)) * u.y;
    o.z = g.z / (1.f + expf(-g.z)) * u.z;
    o.w = g.w / (1.f + expf(-g.w)) * u.w;
    ((float4*)d_G)[i] = o;
}

__global__ void combine_kernel(float* __restrict__ out) {
    int idx = blockIdx.x * blockDim.x + threadIdx.x;
    if (idx >= T_TOKENS * HIDDEN / 4) return;
    int t = idx / (HIDDEN / 4);
    int h4 = idx % (HIDDEN / 4);
    float w0 = d_wgt[2 * t], w1 = d_wgt[2 * t + 1];
    float4 a = ((const float4*)d_Y)[(size_t)(2 * t) * (HIDDEN / 4) + h4];
    float4 b = ((const float4*)d_Y)[(size_t)(2 * t + 1) * (HIDDEN / 4) + h4];
    float4 o;
    o.x = w0 * a.x + w1 * b.x;
    o.y = w0 * a.y + w1 * b.y;
    o.z = w0 * a.z + w1 * b.z;
    o.w = w0 * a.w + w1 * b.w;
    ((float4*)out)[idx] = o;
}

// ---------------- launch ----------------
extern "C" void kernel_launch(void* const* d_in, const int* in_sizes, int n_in,
                              void* d_out, int out_size) {
    const float* x  = (const float*)d_in[0];
    const float* wr = (const float*)d_in[1];
    const float* wg = (const float*)d_in[2];
    const float* wu = (const float*)d_in[3];
    const float* wd = (const float*)d_in[4];
    float* out = (float*)d_out;

    cudaFuncSetAttribute(gemm_tc, cudaFuncAttributeMaxDynamicSharedMemorySize, DYN_BYTES);

    init_kernel<<<1, 32>>>();
    router_kernel<<<T_TOKENS / 8, 256>>>(x, wr);
    compact_kernel<<<NPAIRS / 256, 256>>>();

    // G = x @ Wg^T   (N=INTER, K=HIDDEN)
    dim3 g1(INTER / 256, CAP / 128, NEXP);
    gemm_tc<<<g1, 256, DYN_BYTES>>>(x, wg, INTER, HIDDEN, HIDDEN, 1, 0, 0);
    // U = x @ Wu^T
    gemm_tc<<<g1, 256, DYN_BYTES>>>(x, wu, INTER, HIDDEN, HIDDEN, 1, 0, 1);

    // act = silu(G) * U
    size_t total4 = (size_t)NPAIRS * INTER / 4;
    act_kernel<<<(unsigned)((total4 + 255) / 256), 256>>>();

    // Y = act @ Wd^T  (N=HIDDEN, K=INTER)
    dim3 g3(HIDDEN / 256, CAP / 128, NEXP);
    gemm_tc<<<g3, 256, DYN_BYTES>>>(nullptr, wd, HIDDEN, INTER, INTER, 0, 1, 2);

    combine_kernel<<<(T_TOKENS * HIDDEN / 4) / 256, 256>>>(out);
}

// round 7
// speedup vs baseline: 1.2246x; 1.2246x over previous
#include <cuda_runtime.h>
#include <math.h>
#include <stdint.h>

// Problem constants
#define T_TOKENS 2048
#define HIDDEN   2048
#define INTER    5632
#define NEXP     8
#define TOPK     2
#define NPAIRS   (T_TOKENS * TOPK)   // 4096
#define CAP      2048

// ---------------- device scratch ----------------
__device__ int d_cnt[NEXP];
__device__ int d_list[NEXP * CAP];
__device__ int d_eid[NPAIRS];
__device__ float d_wgt[NPAIRS];

__device__ __align__(16) float d_G[(size_t)NPAIRS * INTER];   // gate, then act (in-place)
__device__ __align__(16) float d_U[(size_t)NPAIRS * INTER];   // up
__device__ __align__(16) float d_Y[(size_t)NPAIRS * HIDDEN];  // per-pair down output

// ---------------- small kernels ----------------
__global__ void init_kernel() {
    if (threadIdx.x < NEXP) d_cnt[threadIdx.x] = 0;
}

__global__ void router_kernel(const float* __restrict__ x, const float* __restrict__ wr) {
    int warp = threadIdx.x >> 5;
    int lane = threadIdx.x & 31;
    int t = blockIdx.x * 8 + warp;
    if (t >= T_TOKENS) return;

    float acc[NEXP];
#pragma unroll
    for (int e = 0; e < NEXP; e++) acc[e] = 0.f;
    const float* xr = x + (size_t)t * HIDDEN;
    for (int j = lane; j < HIDDEN; j += 32) {
        float xv = xr[j];
#pragma unroll
        for (int e = 0; e < NEXP; e++) acc[e] += xv * wr[e * HIDDEN + j];
    }
#pragma unroll
    for (int e = 0; e < NEXP; e++) {
#pragma unroll
        for (int off = 16; off; off >>= 1)
            acc[e] += __shfl_xor_sync(0xffffffffu, acc[e], off);
    }
    if (lane == 0) {
        int e0 = 0;
#pragma unroll
        for (int e = 1; e < NEXP; e++) if (acc[e] > acc[e0]) e0 = e;
        int e1 = -1;
#pragma unroll
        for (int e = 0; e < NEXP; e++) {
            if (e == e0) continue;
            if (e1 < 0 || acc[e] > acc[e1]) e1 = e;
        }
        float v0 = acc[e0], v1 = acc[e1];
        float w1 = 1.f / (1.f + expf(v0 - v1));
        float w0 = 1.f - w1;
        d_eid[2 * t] = e0;  d_eid[2 * t + 1] = e1;
        d_wgt[2 * t] = w0;  d_wgt[2 * t + 1] = w1;
    }
}

__global__ void compact_kernel() {
    int p = blockIdx.x * blockDim.x + threadIdx.x;
    if (p >= NPAIRS) return;
    int e = d_eid[p];
    int pos = atomicAdd(&d_cnt[e], 1);
    d_list[e * CAP + pos] = p;
}

// ---------------- helpers ----------------
__device__ __forceinline__ uint32_t smem_u32(const void* p) {
    uint32_t a;
    asm("{ .reg .u64 t; cvta.to.shared.u64 t, %1; cvt.u32.u64 %0, t; }" : "=r"(a) : "l"(p));
    return a;
}
__device__ __forceinline__ uint32_t tf32r(float x) {
    uint32_t r;
    asm("cvt.rna.tf32.f32 %0, %1;" : "=r"(r) : "f"(x));
    return r;
}
__device__ __forceinline__ void mma_tf32(float* c, const uint32_t* a, const uint32_t* b) {
    asm volatile("mma.sync.aligned.m16n8k8.row.col.f32.tf32.tf32.f32 "
                 "{%0,%1,%2,%3}, {%4,%5,%6,%7}, {%8,%9}, {%0,%1,%2,%3};"
                 : "+f"(c[0]), "+f"(c[1]), "+f"(c[2]), "+f"(c[3])
                 : "r"(a[0]), "r"(a[1]), "r"(a[2]), "r"(a[3]),
                   "r"(b[0]), "r"(b[1]));
}
__device__ __forceinline__ void cp16(uint32_t smem_dst, const void* gptr) {
    asm volatile("cp.async.cg.shared.global [%0], [%1], 16;" :: "r"(smem_dst), "l"(gptr));
}

// ---------------- expert-grouped tf32 tensor GEMM ----------------
// C[pid][n] = sum_k A[pid>>shift][k] * B_e[n][k]
// Tile: BM=128, BN=128, BK=32. 256 threads, 8 warps in 2(m) x 4(n), warp tile 64x32.
// Register double-buffered fragments: load frags(ks+1) under the MMA burst of ks.
#define BK 32
#define SMS 36                                 // padded smem row stride (floats)
#define STAGE_F ((128 + 128) * SMS)            // floats per stage
#define NSTAGE 3

__global__ __launch_bounds__(256, 1)
void gemm_tc(const float* __restrict__ Aext, const float* __restrict__ Ball,
             int N, int K, int lda, int shift, int asel, int csel)
{
    int e = blockIdx.z;
    int n_e = d_cnt[e];
    int mbase = blockIdx.y * 128;
    if (mbase >= n_e) return;
    int nbase = blockIdx.x * 128;

    const float* A = asel ? d_G : Aext;
    float* C = (csel == 0) ? d_G : (csel == 1) ? d_U : d_Y;
    const float* B = Ball + (size_t)e * N * K;

    extern __shared__ float sm[];
    int* s_pid = (int*)(sm + NSTAGE * STAGE_F);
    uint32_t smbase = smem_u32(sm);

    int tid = threadIdx.x;
    int lane = tid & 31;
    int wid = tid >> 5;
    int wm = wid & 1;          // 0..1  (64 rows each)
    int wn = wid >> 1;         // 0..3  (32 cols each)

    if (tid < 128) {
        int lp = mbase + tid;
        s_pid[tid] = d_list[e * CAP + (lp < n_e ? lp : mbase)];
    }
    __syncthreads();

    // loader mapping: 4 chunks/thread per operand; chunk = (row, 16B of k)
    const char* aG[4];
    const char* bG[4];
    uint32_t aS[4], bS[4];
#pragma unroll
    for (int i = 0; i < 4; i++) {
        int idx = tid + i * 256;          // 0..1023
        int row = idx >> 3;
        int c4  = (idx & 7) * 4;
        aG[i] = (const char*)(A + (size_t)(s_pid[row] >> shift) * lda + c4);
        aS[i] = (uint32_t)((row * SMS + c4) * 4);
        bG[i] = (const char*)(B + (size_t)(nbase + row) * K + c4);
        bS[i] = (uint32_t)((128 * SMS + row * SMS + c4) * 4);
    }

    int KT = K / BK;

    auto issue = [&](int st, int kb) {
        uint32_t sb = smbase + (uint32_t)(st * STAGE_F * 4);
        size_t go = (size_t)kb * BK * 4;
#pragma unroll
        for (int i = 0; i < 4; i++) cp16(sb + aS[i], aG[i] + go);
#pragma unroll
        for (int i = 0; i < 4; i++) cp16(sb + bS[i], bG[i] + go);
        asm volatile("cp.async.commit_group;" ::: "memory");
    };

    issue(0, 0);
    issue(1, 1);

    float acc[4][4][4];
#pragma unroll
    for (int mt = 0; mt < 4; mt++)
#pragma unroll
        for (int nt = 0; nt < 4; nt++)
#pragma unroll
            for (int q = 0; q < 4; q++) acc[mt][nt][q] = 0.f;

    int arow = wm * 64 + (lane >> 2);
    int brow = wn * 32 + (lane >> 2);
    int kcol = lane & 3;

    // fragment double buffers
    uint32_t af[2][4][4], bf[2][4][2];

    for (int kb = 0; kb < KT; kb++) {
        int st = kb % NSTAGE;
        if (kb + 2 < KT) {
            __syncthreads();                       // WAR: stage (kb+2)%3 fully consumed
            issue((kb + 2) % NSTAGE, kb + 2);
            asm volatile("cp.async.wait_group 2;" ::: "memory");
        } else if (kb + 1 < KT) {
            asm volatile("cp.async.wait_group 1;" ::: "memory");
        } else {
            asm volatile("cp.async.wait_group 0;" ::: "memory");
        }
        __syncthreads();                           // stage kb visible

        const float* cA = sm + st * STAGE_F;
        const float* cB = cA + 128 * SMS;

        // load fragments for ks = 0 into buffer 0
#pragma unroll
        for (int mt = 0; mt < 4; mt++) {
            const float* p = cA + (arow + mt * 16) * SMS + kcol;
            af[0][mt][0] = tf32r(p[0]);
            af[0][mt][1] = tf32r(p[8 * SMS]);
            af[0][mt][2] = tf32r(p[4]);
            af[0][mt][3] = tf32r(p[8 * SMS + 4]);
        }
#pragma unroll
        for (int nt = 0; nt < 4; nt++) {
            const float* p = cB + (brow + nt * 8) * SMS + kcol;
            bf[0][nt][0] = tf32r(p[0]);
            bf[0][nt][1] = tf32r(p[4]);
        }

#pragma unroll
        for (int ks = 0; ks < 4; ks++) {
            int pb = ks & 1;
            if (ks < 3) {
                int kc = (ks + 1) * 8 + kcol;
#pragma unroll
                for (int mt = 0; mt < 4; mt++) {
                    const float* p = cA + (arow + mt * 16) * SMS + kc;
                    af[pb ^ 1][mt][0] = tf32r(p[0]);
                    af[pb ^ 1][mt][1] = tf32r(p[8 * SMS]);
                    af[pb ^ 1][mt][2] = tf32r(p[4]);
                    af[pb ^ 1][mt][3] = tf32r(p[8 * SMS + 4]);
                }
#pragma unroll
                for (int nt = 0; nt < 4; nt++) {
                    const float* p = cB + (brow + nt * 8) * SMS + kc;
                    bf[pb ^ 1][nt][0] = tf32r(p[0]);
                    bf[pb ^ 1][nt][1] = tf32r(p[4]);
                }
            }
#pragma unroll
            for (int mt = 0; mt < 4; mt++)
#pragma unroll
                for (int nt = 0; nt < 4; nt++)
                    mma_tf32(acc[mt][nt], af[pb][mt], bf[pb][nt]);
        }
    }

    // ---- epilogue: scatter accum rows via pid list ----
    int gid = lane >> 2;      // 0..7
    int tig = lane & 3;       // 0..3
#pragma unroll
    for (int mt = 0; mt < 4; mt++) {
        int mrow0 = wm * 64 + mt * 16 + gid;
        int mrow1 = mrow0 + 8;
        bool v0 = (mbase + mrow0) < n_e;
        bool v1 = (mbase + mrow1) < n_e;
        float* c0 = v0 ? (C + (size_t)s_pid[mrow0] * N + nbase + wn * 32 + tig * 2) : (float*)0;
        float* c1 = v1 ? (C + (size_t)s_pid[mrow1] * N + nbase + wn * 32 + tig * 2) : (float*)0;
#pragma unroll
        for (int nt = 0; nt < 4; nt++) {
            if (v0) *(float2*)(c0 + nt * 8) = make_float2(acc[mt][nt][0], acc[mt][nt][1]);
            if (v1) *(float2*)(c1 + nt * 8) = make_float2(acc[mt][nt][2], acc[mt][nt][3]);
        }
    }
}

#define DYN_BYTES (NSTAGE * STAGE_F * 4 + 128 * 4 + 16)

// ---------------- elementwise ----------------
__global__ void act_kernel() {
    size_t i = (size_t)blockIdx.x * blockDim.x + threadIdx.x;
    if (i >= (size_t)NPAIRS * INTER / 4) return;
    float4 g = ((const float4*)d_G)[i];
    float4 u = ((const float4*)d_U)[i];
    float4 o;
    o.x = g.x / (1.f + expf(-g.x)) * u.x;
    o.y = g.y / (1.f + expf(-g.y)) * u.y;
    o.z = g.z / (1.f + expf(-g.z)) * u.z;
    o.w = g.w / (1.f + expf(-g.w)) * u.w;
    ((float4*)d_G)[i] = o;
}

__global__ void combine_kernel(float* __restrict__ out) {
    int idx = blockIdx.x * blockDim.x + threadIdx.x;
    if (idx >= T_TOKENS * HIDDEN / 4) return;
    int t = idx / (HIDDEN / 4);
    int h4 = idx % (HIDDEN / 4);
    float w0 = d_wgt[2 * t], w1 = d_wgt[2 * t + 1];
    float4 a = ((const float4*)d_Y)[(size_t)(2 * t) * (HIDDEN / 4) + h4];
    float4 b = ((const float4*)d_Y)[(size_t)(2 * t + 1) * (HIDDEN / 4) + h4];
    float4 o;
    o.x = w0 * a.x + w1 * b.x;
    o.y = w0 * a.y + w1 * b.y;
    o.z = w0 * a.z + w1 * b.z;
    o.w = w0 * a.w + w1 * b.w;
    ((float4*)out)[idx] = o;
}

// ---------------- launch ----------------
extern "C" void kernel_launch(void* const* d_in, const int* in_sizes, int n_in,
                              void* d_out, int out_size) {
    const float* x  = (const float*)d_in[0];
    const float* wr = (const float*)d_in[1];
    const float* wg = (const float*)d_in[2];
    const float* wu = (const float*)d_in[3];
    const float* wd = (const float*)d_in[4];
    float* out = (float*)d_out;

    cudaFuncSetAttribute(gemm_tc, cudaFuncAttributeMaxDynamicSharedMemorySize, DYN_BYTES);

    init_kernel<<<1, 32>>>();
    router_kernel<<<T_TOKENS / 8, 256>>>(x, wr);
    compact_kernel<<<NPAIRS / 256, 256>>>();

    // G = x @ Wg^T   (N=INTER, K=HIDDEN)
    dim3 g1(INTER / 128, CAP / 128, NEXP);
    gemm_tc<<<g1, 256, DYN_BYTES>>>(x, wg, INTER, HIDDEN, HIDDEN, 1, 0, 0);
    // U = x @ Wu^T
    gemm_tc<<<g1, 256, DYN_BYTES>>>(x, wu, INTER, HIDDEN, HIDDEN, 1, 0, 1);

    // act = silu(G) * U
    size_t total4 = (size_t)NPAIRS * INTER / 4;
    act_kernel<<<(unsigned)((total4 + 255) / 256), 256>>>();

    // Y = act @ Wd^T  (N=HIDDEN, K=INTER)
    dim3 g3(HIDDEN / 128, CAP / 128, NEXP);
    gemm_tc<<<g3, 256, DYN_BYTES>>>(nullptr, wd, HIDDEN, INTER, INTER, 0, 1, 2);

    combine_kernel<<<(T_TOKENS * HIDDEN / 4) / 256, 256>>>(out);
}

// round 9
// speedup vs baseline: 1.5334x; 1.2522x over previous
#include <cuda_runtime.h>
#include <math.h>
#include <stdint.h>

// Problem constants
#define T_TOKENS 2048
#define HIDDEN   2048
#define INTER    5632
#define NEXP     8
#define TOPK     2
#define NPAIRS   (T_TOKENS * TOPK)   // 4096
#define CAP      2048

// ---------------- device scratch ----------------
__device__ int d_cnt[NEXP];
__device__ int d_list[NEXP * CAP];
__device__ int d_eid[NPAIRS];
__device__ float d_wgt[NPAIRS];

__device__ __align__(16) float d_Xr[(size_t)T_TOKENS * HIDDEN]; // tf32-rounded x
__device__ __align__(16) float d_G[(size_t)NPAIRS * INTER];   // gate, then act (in-place)
__device__ __align__(16) float d_U[(size_t)NPAIRS * INTER];   // up
__device__ __align__(16) float d_Y[(size_t)NPAIRS * HIDDEN];  // per-pair down output

// ---------------- small kernels ----------------
__global__ void init_kernel() {
    if (threadIdx.x < NEXP) d_cnt[threadIdx.x] = 0;
}

__global__ void router_kernel(const float* __restrict__ x, const float* __restrict__ wr) {
    int warp = threadIdx.x >> 5;
    int lane = threadIdx.x & 31;
    int t = blockIdx.x * 8 + warp;
    if (t >= T_TOKENS) return;

    float acc[NEXP];
#pragma unroll
    for (int e = 0; e < NEXP; e++) acc[e] = 0.f;
    const float* xr = x + (size_t)t * HIDDEN;
    for (int j = lane; j < HIDDEN; j += 32) {
        float xv = xr[j];
#pragma unroll
        for (int e = 0; e < NEXP; e++) acc[e] += xv * wr[e * HIDDEN + j];
    }
#pragma unroll
    for (int e = 0; e < NEXP; e++) {
#pragma unroll
        for (int off = 16; off; off >>= 1)
            acc[e] += __shfl_xor_sync(0xffffffffu, acc[e], off);
    }
    if (lane == 0) {
        int e0 = 0;
#pragma unroll
        for (int e = 1; e < NEXP; e++) if (acc[e] > acc[e0]) e0 = e;
        int e1 = -1;
#pragma unroll
        for (int e = 0; e < NEXP; e++) {
            if (e == e0) continue;
            if (e1 < 0 || acc[e] > acc[e1]) e1 = e;
        }
        float v0 = acc[e0], v1 = acc[e1];
        float w1 = 1.f / (1.f + expf(v0 - v1));
        float w0 = 1.f - w1;
        d_eid[2 * t] = e0;  d_eid[2 * t + 1] = e1;
        d_wgt[2 * t] = w0;  d_wgt[2 * t + 1] = w1;
    }
}

__global__ void compact_kernel() {
    int p = blockIdx.x * blockDim.x + threadIdx.x;
    if (p >= NPAIRS) return;
    int e = d_eid[p];
    int pos = atomicAdd(&d_cnt[e], 1);
    d_list[e * CAP + pos] = p;
}

// ---------------- helpers ----------------
__device__ __forceinline__ uint32_t smem_u32(const void* p) {
    uint32_t a;
    asm("{ .reg .u64 t; cvta.to.shared.u64 t, %1; cvt.u32.u64 %0, t; }" : "=r"(a) : "l"(p));
    return a;
}
__device__ __forceinline__ uint32_t tf32r(float x) {
    uint32_t r;
    asm("cvt.rna.tf32.f32 %0, %1;" : "=r"(r) : "f"(x));
    return r;
}
__device__ __forceinline__ float tf32rf(float x) {
    uint32_t r = tf32r(x);
    return __uint_as_float(r);
}
__device__ __forceinline__ void mma_tf32(float* c, const uint32_t* a, const uint32_t* b) {
    asm volatile("mma.sync.aligned.m16n8k8.row.col.f32.tf32.tf32.f32 "
                 "{%0,%1,%2,%3}, {%4,%5,%6,%7}, {%8,%9}, {%0,%1,%2,%3};"
                 : "+f"(c[0]), "+f"(c[1]), "+f"(c[2]), "+f"(c[3])
                 : "r"(a[0]), "r"(a[1]), "r"(a[2]), "r"(a[3]),
                   "r"(b[0]), "r"(b[1]));
}
__device__ __forceinline__ void ldm4(uint32_t* d, uint32_t addr) {
    asm volatile("ldmatrix.sync.aligned.m8n8.x4.shared.b16 {%0,%1,%2,%3}, [%4];"
                 : "=r"(d[0]), "=r"(d[1]), "=r"(d[2]), "=r"(d[3]) : "r"(addr));
}
__device__ __forceinline__ void cp16(uint32_t smem_dst, const void* gptr) {
    asm volatile("cp.async.cg.shared.global [%0], [%1], 16;" :: "r"(smem_dst), "l"(gptr));
}

// ---------------- expert-grouped tf32 tensor GEMM (ldmatrix fragments) ----------------
// C[pid][n] = sum_k A[pid>>shift][k] * B_e[n][k]
// Tile: BM=128, BN=256, BK=32. 256 threads, 8 warps in 2(m) x 4(n), warp tile 64x64.
// A source selected IN KERNEL: asel 0 -> d_Xr (tf32-rounded x), 1 -> d_G (tf32-rounded act).
// B (weights) cvt'd on fragments post-ldmatrix.
#define BK 32
#define SMS 36                                 // padded smem row stride (floats); 144B, 16B-aligned
#define STAGE_F ((128 + 256) * SMS)            // floats per stage: A(128) + B(256) rows
#define NSTAGE 3

__global__ __launch_bounds__(256, 1)
void gemm_tc(const float* __restrict__ Ball,
             int N, int K, int lda, int shift, int asel, int csel)
{
    int e = blockIdx.z;
    int n_e = d_cnt[e];
    int mbase = blockIdx.y * 128;
    if (mbase >= n_e) return;
    int nbase = blockIdx.x * 256;

    const float* A = asel ? d_G : d_Xr;                 // device-side symbol resolution
    float* C = (csel == 0) ? d_G : (csel == 1) ? d_U : d_Y;
    const float* B = Ball + (size_t)e * N * K;

    extern __shared__ float sm[];
    int* s_pid = (int*)(sm + NSTAGE * STAGE_F);
    uint32_t smbase = smem_u32(sm);

    int tid = threadIdx.x;
    int lane = tid & 31;
    int wid = tid >> 5;
    int wm = wid & 1;          // 0..1  (64 rows each)
    int wn = wid >> 1;         // 0..3  (64 cols each)

    if (tid < 128) {
        int lp = mbase + tid;
        s_pid[tid] = d_list[e * CAP + (lp < n_e ? lp : mbase)];
    }
    __syncthreads();

    // loader mapping: A 4 chunks/thread, B 8 chunks/thread; chunk = (row, 16B of k)
    const char* aG[4];
    const char* bG[8];
    uint32_t aS[4], bS[8];
#pragma unroll
    for (int i = 0; i < 4; i++) {
        int idx = tid + i * 256;          // 0..1023
        int row = idx >> 3;
        int c4  = (idx & 7) * 4;
        aG[i] = (const char*)(A + (size_t)(s_pid[row] >> shift) * lda + c4);
        aS[i] = (uint32_t)((row * SMS + c4) * 4);
    }
#pragma unroll
    for (int i = 0; i < 8; i++) {
        int idx = tid + i * 256;          // 0..2047
        int row = idx >> 3;
        int c4  = (idx & 7) * 4;
        bG[i] = (const char*)(B + (size_t)(nbase + row) * K + c4);
        bS[i] = (uint32_t)((128 * SMS + row * SMS + c4) * 4);
    }

    int KT = K / BK;

    auto issue = [&](int st, int kb) {
        uint32_t sb = smbase + (uint32_t)(st * STAGE_F * 4);
        size_t go = (size_t)kb * BK * 4;
#pragma unroll
        for (int i = 0; i < 4; i++) cp16(sb + aS[i], aG[i] + go);
#pragma unroll
        for (int i = 0; i < 8; i++) cp16(sb + bS[i], bG[i] + go);
        asm volatile("cp.async.commit_group;" ::: "memory");
    };

    issue(0, 0);
    issue(1, 1);

    float acc[4][8][4];
#pragma unroll
    for (int mt = 0; mt < 4; mt++)
#pragma unroll
        for (int nt = 0; nt < 8; nt++)
#pragma unroll
            for (int q = 0; q < 4; q++) acc[mt][nt][q] = 0.f;

    // ---- ldmatrix per-lane addresses (byte offsets within a stage) ----
    // lane -> (lg = lane>>3 tile index, lr = lane&7 row-within-tile)
    int lg = lane >> 3, lr = lane & 7;
    // A mt tile: matrices g0=(r0-7,k0-3) g1=(r8-15,k0-3) g2=(r0-7,k4-7) g3=(r8-15,k4-7)
    uint32_t aoff[4];
#pragma unroll
    for (int mt = 0; mt < 4; mt++) {
        int row = wm * 64 + mt * 16 + ((lg & 1) << 3) + lr;
        int col = (lg >> 1) << 2;
        aoff[mt] = (uint32_t)((row * SMS + col) * 4);
    }
    // B ntp tile: matrices g0=(n0-7,k0-3) g1=(n0-7,k4-7) g2=(n8-15,k0-3) g3=(n8-15,k4-7)
    uint32_t boff[4];
#pragma unroll
    for (int ntp = 0; ntp < 4; ntp++) {
        int row = 128 + wn * 64 + ntp * 16 + ((lg >> 1) << 3) + lr;
        int col = (lg & 1) << 2;
        boff[ntp] = (uint32_t)((row * SMS + col) * 4);
    }

    for (int kb = 0; kb < KT; kb++) {
        int st = kb % NSTAGE;
        if (kb + 2 < KT) {
            __syncthreads();                       // WAR: stage (kb+2)%3 fully consumed
            issue((kb + 2) % NSTAGE, kb + 2);
            asm volatile("cp.async.wait_group 2;" ::: "memory");
        } else if (kb + 1 < KT) {
            asm volatile("cp.async.wait_group 1;" ::: "memory");
        } else {
            asm volatile("cp.async.wait_group 0;" ::: "memory");
        }
        __syncthreads();                           // stage kb visible

        uint32_t sb32 = smbase + (uint32_t)(st * STAGE_F * 4);
#pragma unroll
        for (int ks = 0; ks < 4; ks++) {
            uint32_t kbyte = (uint32_t)(ks * 32);  // 8 floats
            uint32_t af[4][4];
            uint32_t bfr[4][4];
#pragma unroll
            for (int mt = 0; mt < 4; mt++) ldm4(af[mt], sb32 + aoff[mt] + kbyte);
#pragma unroll
            for (int ntp = 0; ntp < 4; ntp++) ldm4(bfr[ntp], sb32 + boff[ntp] + kbyte);
            // round B fragments (A is pre-rounded)
#pragma unroll
            for (int ntp = 0; ntp < 4; ntp++)
#pragma unroll
                for (int q = 0; q < 4; q++)
                    bfr[ntp][q] = tf32r(__uint_as_float(bfr[ntp][q]));
#pragma unroll
            for (int mt = 0; mt < 4; mt++)
#pragma unroll
                for (int ntp = 0; ntp < 4; ntp++) {
                    mma_tf32(acc[mt][2 * ntp],     af[mt], &bfr[ntp][0]);
                    mma_tf32(acc[mt][2 * ntp + 1], af[mt], &bfr[ntp][2]);
                }
        }
    }

    // ---- epilogue: scatter accum rows via pid list ----
    int gid = lane >> 2;      // 0..7
    int tig = lane & 3;       // 0..3
#pragma unroll
    for (int mt = 0; mt < 4; mt++) {
        int mrow0 = wm * 64 + mt * 16 + gid;
        int mrow1 = mrow0 + 8;
        bool v0 = (mbase + mrow0) < n_e;
        bool v1 = (mbase + mrow1) < n_e;
        float* c0 = v0 ? (C + (size_t)s_pid[mrow0] * N + nbase + wn * 64 + tig * 2) : (float*)0;
        float* c1 = v1 ? (C + (size_t)s_pid[mrow1] * N + nbase + wn * 64 + tig * 2) : (float*)0;
#pragma unroll
        for (int nt = 0; nt < 8; nt++) {
            if (v0) *(float2*)(c0 + nt * 8) = make_float2(acc[mt][nt][0], acc[mt][nt][1]);
            if (v1) *(float2*)(c1 + nt * 8) = make_float2(acc[mt][nt][2], acc[mt][nt][3]);
        }
    }
}

#define DYN_BYTES (NSTAGE * STAGE_F * 4 + 128 * 4 + 16)

// ---------------- elementwise ----------------
__global__ void roundx_kernel(const float* __restrict__ x) {
    int i = blockIdx.x * blockDim.x + threadIdx.x;
    if (i >= T_TOKENS * HIDDEN / 4) return;
    float4 v = ((const float4*)x)[i];
    float4 o;
    o.x = tf32rf(v.x); o.y = tf32rf(v.y); o.z = tf32rf(v.z); o.w = tf32rf(v.w);
    ((float4*)d_Xr)[i] = o;
}

// act = tf32_round(silu(G) * U), written in place into G
__global__ void act_kernel() {
    size_t i = (size_t)blockIdx.x * blockDim.x + threadIdx.x;
    if (i >= (size_t)NPAIRS * INTER / 4) return;
    float4 g = ((const float4*)d_G)[i];
    float4 u = ((const float4*)d_U)[i];
    float4 o;
    o.x = tf32rf(g.x / (1.f + expf(-g.x)) * u.x);
    o.y = tf32rf(g.y / (1.f + expf(-g.y)) * u.y);
    o.z = tf32rf(g.z / (1.f + expf(-g.z)) * u.z);
    o.w = tf32rf(g.w / (1.f + expf(-g.w)) * u.w);
    ((float4*)d_G)[i] = o;
}

__global__ void combine_kernel(float* __restrict__ out) {
    int idx = blockIdx.x * blockDim.x + threadIdx.x;
    if (idx >= T_TOKENS * HIDDEN / 4) return;
    int t = idx / (HIDDEN / 4);
    int h4 = idx % (HIDDEN / 4);
    float w0 = d_wgt[2 * t], w1 = d_wgt[2 * t + 1];
    float4 a = ((const float4*)d_Y)[(size_t)(2 * t) * (HIDDEN / 4) + h4];
    float4 b = ((const float4*)d_Y)[(size_t)(2 * t + 1) * (HIDDEN / 4) + h4];
    float4 o;
    o.x = w0 * a.x + w1 * b.x;
    o.y = w0 * a.y + w1 * b.y;
    o.z = w0 * a.z + w1 * b.z;
    o.w = w0 * a.w + w1 * b.w;
    ((float4*)out)[idx] = o;
}

// ---------------- launch ----------------
extern "C" void kernel_launch(void* const* d_in, const int* in_sizes, int n_in,
                              void* d_out, int out_size) {
    const float* x  = (const float*)d_in[0];
    const float* wr = (const float*)d_in[1];
    const float* wg = (const float*)d_in[2];
    const float* wu = (const float*)d_in[3];
    const float* wd = (const float*)d_in[4];
    float* out = (float*)d_out;

    cudaFuncSetAttribute(gemm_tc, cudaFuncAttributeMaxDynamicSharedMemorySize, DYN_BYTES);

    init_kernel<<<1, 32>>>();
    router_kernel<<<T_TOKENS / 8, 256>>>(x, wr);
    compact_kernel<<<NPAIRS / 256, 256>>>();
    roundx_kernel<<<(T_TOKENS * HIDDEN / 4) / 256, 256>>>(x);

    // G = x @ Wg^T   (N=INTER, K=HIDDEN)   A = d_Xr (asel 0)
    dim3 g1(INTER / 256, CAP / 128, NEXP);
    gemm_tc<<<g1, 256, DYN_BYTES>>>(wg, INTER, HIDDEN, HIDDEN, 1, 0, 0);
    // U = x @ Wu^T
    gemm_tc<<<g1, 256, DYN_BYTES>>>(wu, INTER, HIDDEN, HIDDEN, 1, 0, 1);

    // act = tf32(silu(G) * U)
    size_t total4 = (size_t)NPAIRS * INTER / 4;
    act_kernel<<<(unsigned)((total4 + 255) / 256), 256>>>();

    // Y = act @ Wd^T  (N=HIDDEN, K=INTER)  A = d_G (asel 1)
    dim3 g3(HIDDEN / 256, CAP / 128, NEXP);
    gemm_tc<<<g3, 256, DYN_BYTES>>>(wd, HIDDEN, INTER, INTER, 0, 1, 2);

    combine_kernel<<<(T_TOKENS * HIDDEN / 4) / 256, 256>>>(out);
}

// round 10
// speedup vs baseline: 1.5374x; 1.0026x over previous
#include <cuda_runtime.h>
#include <math.h>
#include <stdint.h>

// Problem constants
#define T_TOKENS 2048
#define HIDDEN   2048
#define INTER    5632
#define NEXP     8
#define TOPK     2
#define NPAIRS   (T_TOKENS * TOPK)   // 4096
#define CAP      2048

// ---------------- device scratch ----------------
__device__ int d_cnt[NEXP];
__device__ int d_list[NEXP * CAP];
__device__ int d_eid[NPAIRS];
__device__ float d_wgt[NPAIRS];

__device__ __align__(16) float d_Xr[(size_t)T_TOKENS * HIDDEN]; // tf32-rounded x
__device__ __align__(16) float d_G[(size_t)NPAIRS * INTER];   // gate, then act (in-place)
__device__ __align__(16) float d_U[(size_t)NPAIRS * INTER];   // up
__device__ __align__(16) float d_Y[(size_t)NPAIRS * HIDDEN];  // per-pair down output

// ---------------- small kernels ----------------
__global__ void init_kernel() {
    if (threadIdx.x < NEXP) d_cnt[threadIdx.x] = 0;
}

__global__ void router_kernel(const float* __restrict__ x, const float* __restrict__ wr) {
    int warp = threadIdx.x >> 5;
    int lane = threadIdx.x & 31;
    int t = blockIdx.x * 8 + warp;
    if (t >= T_TOKENS) return;

    float acc[NEXP];
#pragma unroll
    for (int e = 0; e < NEXP; e++) acc[e] = 0.f;
    const float* xr = x + (size_t)t * HIDDEN;
    for (int j = lane; j < HIDDEN; j += 32) {
        float xv = xr[j];
#pragma unroll
        for (int e = 0; e < NEXP; e++) acc[e] += xv * wr[e * HIDDEN + j];
    }
#pragma unroll
    for (int e = 0; e < NEXP; e++) {
#pragma unroll
        for (int off = 16; off; off >>= 1)
            acc[e] += __shfl_xor_sync(0xffffffffu, acc[e], off);
    }
    if (lane == 0) {
        int e0 = 0;
#pragma unroll
        for (int e = 1; e < NEXP; e++) if (acc[e] > acc[e0]) e0 = e;
        int e1 = -1;
#pragma unroll
        for (int e = 0; e < NEXP; e++) {
            if (e == e0) continue;
            if (e1 < 0 || acc[e] > acc[e1]) e1 = e;
        }
        float v0 = acc[e0], v1 = acc[e1];
        float w1 = 1.f / (1.f + expf(v0 - v1));
        float w0 = 1.f - w1;
        d_eid[2 * t] = e0;  d_eid[2 * t + 1] = e1;
        d_wgt[2 * t] = w0;  d_wgt[2 * t + 1] = w1;
    }
}

__global__ void compact_kernel() {
    int p = blockIdx.x * blockDim.x + threadIdx.x;
    if (p >= NPAIRS) return;
    int e = d_eid[p];
    int pos = atomicAdd(&d_cnt[e], 1);
    d_list[e * CAP + pos] = p;
}

// ---------------- helpers ----------------
__device__ __forceinline__ uint32_t smem_u32(const void* p) {
    uint32_t a;
    asm("{ .reg .u64 t; cvta.to.shared.u64 t, %1; cvt.u32.u64 %0, t; }" : "=r"(a) : "l"(p));
    return a;
}
__device__ __forceinline__ uint32_t tf32r(float x) {
    uint32_t r;
    asm("cvt.rna.tf32.f32 %0, %1;" : "=r"(r) : "f"(x));
    return r;
}
__device__ __forceinline__ float tf32rf(float x) {
    uint32_t r = tf32r(x);
    return __uint_as_float(r);
}
__device__ __forceinline__ void mma_tf32(float* c, const uint32_t* a, const uint32_t* b) {
    asm volatile("mma.sync.aligned.m16n8k8.row.col.f32.tf32.tf32.f32 "
                 "{%0,%1,%2,%3}, {%4,%5,%6,%7}, {%8,%9}, {%0,%1,%2,%3};"
                 : "+f"(c[0]), "+f"(c[1]), "+f"(c[2]), "+f"(c[3])
                 : "r"(a[0]), "r"(a[1]), "r"(a[2]), "r"(a[3]),
                   "r"(b[0]), "r"(b[1]));
}
__device__ __forceinline__ void ldm4(uint32_t* d, uint32_t addr) {
    asm volatile("ldmatrix.sync.aligned.m8n8.x4.shared.b16 {%0,%1,%2,%3}, [%4];"
                 : "=r"(d[0]), "=r"(d[1]), "=r"(d[2]), "=r"(d[3]) : "r"(addr));
}
__device__ __forceinline__ void cp16(uint32_t smem_dst, const void* gptr) {
    asm volatile("cp.async.cg.shared.global [%0], [%1], 16;" :: "r"(smem_dst), "l"(gptr));
}

// ---------------- expert-grouped tf32 tensor GEMM (ldmatrix + frag pipeline) ----------------
// C[pid][n] = sum_k A[pid>>shift][k] * B_e[n][k]
// Tile: BM=128, BN=256, BK=32. 256 threads, 8 warps in 2(m) x 4(n), warp tile 64x64.
// A source selected IN KERNEL: asel 0 -> d_Xr, 1 -> d_G. B cvt'd on fragments post-ldmatrix.
// Fragments double-buffered across ks: ldm(ks+1) -> MMA(ks) -> cvt(ks+1).
#define BK 32
#define SMS 36                                 // padded smem row stride (floats); 144B
#define STAGE_F ((128 + 256) * SMS)            // floats per stage
#define NSTAGE 3

__global__ __launch_bounds__(256, 1)
void gemm_tc(const float* __restrict__ Ball,
             int N, int K, int lda, int shift, int asel, int csel)
{
    int e = blockIdx.z;
    int n_e = d_cnt[e];
    int mbase = blockIdx.y * 128;
    if (mbase >= n_e) return;
    int nbase = blockIdx.x * 256;

    const float* A = asel ? d_G : d_Xr;
    float* C = (csel == 0) ? d_G : (csel == 1) ? d_U : d_Y;
    const float* B = Ball + (size_t)e * N * K;

    extern __shared__ float sm[];
    int* s_pid = (int*)(sm + NSTAGE * STAGE_F);
    uint32_t smbase = smem_u32(sm);

    int tid = threadIdx.x;
    int lane = tid & 31;
    int wid = tid >> 5;
    int wm = wid & 1;
    int wn = wid >> 1;

    if (tid < 128) {
        int lp = mbase + tid;
        s_pid[tid] = d_list[e * CAP + (lp < n_e ? lp : mbase)];
    }
    __syncthreads();

    const char* aG[4];
    const char* bG[8];
    uint32_t aS[4], bS[8];
#pragma unroll
    for (int i = 0; i < 4; i++) {
        int idx = tid + i * 256;
        int row = idx >> 3;
        int c4  = (idx & 7) * 4;
        aG[i] = (const char*)(A + (size_t)(s_pid[row] >> shift) * lda + c4);
        aS[i] = (uint32_t)((row * SMS + c4) * 4);
    }
#pragma unroll
    for (int i = 0; i < 8; i++) {
        int idx = tid + i * 256;
        int row = idx >> 3;
        int c4  = (idx & 7) * 4;
        bG[i] = (const char*)(B + (size_t)(nbase + row) * K + c4);
        bS[i] = (uint32_t)((128 * SMS + row * SMS + c4) * 4);
    }

    int KT = K / BK;

    auto issue = [&](int st, int kb) {
        uint32_t sb = smbase + (uint32_t)(st * STAGE_F * 4);
        size_t go = (size_t)kb * BK * 4;
#pragma unroll
        for (int i = 0; i < 4; i++) cp16(sb + aS[i], aG[i] + go);
#pragma unroll
        for (int i = 0; i < 8; i++) cp16(sb + bS[i], bG[i] + go);
        asm volatile("cp.async.commit_group;" ::: "memory");
    };

    issue(0, 0);
    issue(1, 1);

    float acc[4][8][4];
#pragma unroll
    for (int mt = 0; mt < 4; mt++)
#pragma unroll
        for (int nt = 0; nt < 8; nt++)
#pragma unroll
            for (int q = 0; q < 4; q++) acc[mt][nt][q] = 0.f;

    // ldmatrix per-lane addresses (byte offsets within a stage)
    int lg = lane >> 3, lr = lane & 7;
    uint32_t aoff[4];
#pragma unroll
    for (int mt = 0; mt < 4; mt++) {
        int row = wm * 64 + mt * 16 + ((lg & 1) << 3) + lr;
        int col = (lg >> 1) << 2;
        aoff[mt] = (uint32_t)((row * SMS + col) * 4);
    }
    uint32_t boff[4];
#pragma unroll
    for (int ntp = 0; ntp < 4; ntp++) {
        int row = 128 + wn * 64 + ntp * 16 + ((lg >> 1) << 3) + lr;
        int col = (lg & 1) << 2;
        boff[ntp] = (uint32_t)((row * SMS + col) * 4);
    }

    // fragment double buffers
    uint32_t af[2][4][4], bfr[2][4][4];

    for (int kb = 0; kb < KT; kb++) {
        int st = kb % NSTAGE;
        if (kb + 2 < KT) {
            __syncthreads();
            issue((kb + 2) % NSTAGE, kb + 2);
            asm volatile("cp.async.wait_group 2;" ::: "memory");
        } else if (kb + 1 < KT) {
            asm volatile("cp.async.wait_group 1;" ::: "memory");
        } else {
            asm volatile("cp.async.wait_group 0;" ::: "memory");
        }
        __syncthreads();

        uint32_t sb32 = smbase + (uint32_t)(st * STAGE_F * 4);

        // prime ks=0 fragments into buffer 0
#pragma unroll
        for (int mt = 0; mt < 4; mt++) ldm4(af[0][mt], sb32 + aoff[mt]);
#pragma unroll
        for (int ntp = 0; ntp < 4; ntp++) ldm4(bfr[0][ntp], sb32 + boff[ntp]);
#pragma unroll
        for (int ntp = 0; ntp < 4; ntp++)
#pragma unroll
            for (int q = 0; q < 4; q++)
                bfr[0][ntp][q] = tf32r(__uint_as_float(bfr[0][ntp][q]));

#pragma unroll
        for (int ks = 0; ks < 4; ks++) {
            int pb = ks & 1;
            // 1) issue ldmatrix for ks+1 (latency hides under MMA burst below)
            if (ks < 3) {
                uint32_t kbyte = (uint32_t)((ks + 1) * 32);
#pragma unroll
                for (int mt = 0; mt < 4; mt++) ldm4(af[pb ^ 1][mt], sb32 + aoff[mt] + kbyte);
#pragma unroll
                for (int ntp = 0; ntp < 4; ntp++) ldm4(bfr[pb ^ 1][ntp], sb32 + boff[ntp] + kbyte);
            }
            // 2) MMA burst for ks
#pragma unroll
            for (int mt = 0; mt < 4; mt++)
#pragma unroll
                for (int ntp = 0; ntp < 4; ntp++) {
                    mma_tf32(acc[mt][2 * ntp],     af[pb][mt], &bfr[pb][ntp][0]);
                    mma_tf32(acc[mt][2 * ntp + 1], af[pb][mt], &bfr[pb][ntp][2]);
                }
            // 3) cvt B fragments for ks+1 (ldmatrix results ready by now)
            if (ks < 3) {
#pragma unroll
                for (int ntp = 0; ntp < 4; ntp++)
#pragma unroll
                    for (int q = 0; q < 4; q++)
                        bfr[pb ^ 1][ntp][q] = tf32r(__uint_as_float(bfr[pb ^ 1][ntp][q]));
            }
        }
    }

    // ---- epilogue: scatter accum rows via pid list ----
    int gid = lane >> 2;
    int tig = lane & 3;
#pragma unroll
    for (int mt = 0; mt < 4; mt++) {
        int mrow0 = wm * 64 + mt * 16 + gid;
        int mrow1 = mrow0 + 8;
        bool v0 = (mbase + mrow0) < n_e;
        bool v1 = (mbase + mrow1) < n_e;
        float* c0 = v0 ? (C + (size_t)s_pid[mrow0] * N + nbase + wn * 64 + tig * 2) : (float*)0;
        float* c1 = v1 ? (C + (size_t)s_pid[mrow1] * N + nbase + wn * 64 + tig * 2) : (float*)0;
#pragma unroll
        for (int nt = 0; nt < 8; nt++) {
            if (v0) *(float2*)(c0 + nt * 8) = make_float2(acc[mt][nt][0], acc[mt][nt][1]);
            if (v1) *(float2*)(c1 + nt * 8) = make_float2(acc[mt][nt][2], acc[mt][nt][3]);
        }
    }
}

#define DYN_BYTES (NSTAGE * STAGE_F * 4 + 128 * 4 + 16)

// ---------------- elementwise ----------------
__global__ void roundx_kernel(const float* __restrict__ x) {
    int i = blockIdx.x * blockDim.x + threadIdx.x;
    if (i >= T_TOKENS * HIDDEN / 4) return;
    float4 v = ((const float4*)x)[i];
    float4 o;
    o.x = tf32rf(v.x); o.y = tf32rf(v.y); o.z = tf32rf(v.z); o.w = tf32rf(v.w);
    ((float4*)d_Xr)[i] = o;
}

// act = tf32_round(silu(G) * U), written in place into G
__global__ void act_kernel() {
    size_t i = (size_t)blockIdx.x * blockDim.x + threadIdx.x;
    if (i >= (size_t)NPAIRS * INTER / 4) return;
    float4 g = ((const float4*)d_G)[i];
    float4 u = ((const float4*)d_U)[i];
    float4 o;
    o.x = tf32rf(g.x / (1.f + expf(-g.x)) * u.x);
    o.y = tf32rf(g.y / (1.f + expf(-g.y)) * u.y);
    o.z = tf32rf(g.z / (1.f + expf(-g.z)) * u.z);
    o.w = tf32rf(g.w / (1.f + expf(-g.w)) * u.w);
    ((float4*)d_G)[i] = o;
}

__global__ void combine_kernel(float* __restrict__ out) {
    int idx = blockIdx.x * blockDim.x + threadIdx.x;
    if (idx >= T_TOKENS * HIDDEN / 4) return;
    int t = idx / (HIDDEN / 4);
    int h4 = idx % (HIDDEN / 4);
    float w0 = d_wgt[2 * t], w1 = d_wgt[2 * t + 1];
    float4 a = ((const float4*)d_Y)[(size_t)(2 * t) * (HIDDEN / 4) + h4];
    float4 b = ((const float4*)d_Y)[(size_t)(2 * t + 1) * (HIDDEN / 4) + h4];
    float4 o;
    o.x = w0 * a.x + w1 * b.x;
    o.y = w0 * a.y + w1 * b.y;
    o.z = w0 * a.z + w1 * b.z;
    o.w = w0 * a.w + w1 * b.w;
    ((float4*)out)[idx] = o;
}

// ---------------- launch ----------------
extern "C" void kernel_launch(void* const* d_in, const int* in_sizes, int n_in,
                              void* d_out, int out_size) {
    const float* x  = (const float*)d_in[0];
    const float* wr = (const float*)d_in[1];
    const float* wg = (const float*)d_in[2];
    const float* wu = (const float*)d_in[3];
    const float* wd = (const float*)d_in[4];
    float* out = (float*)d_out;

    cudaFuncSetAttribute(gemm_tc, cudaFuncAttributeMaxDynamicSharedMemorySize, DYN_BYTES);

    init_kernel<<<1, 32>>>();
    router_kernel<<<T_TOKENS / 8, 256>>>(x, wr);
    compact_kernel<<<NPAIRS / 256, 256>>>();
    roundx_kernel<<<(T_TOKENS * HIDDEN / 4) / 256, 256>>>(x);

    // G = x @ Wg^T   (N=INTER, K=HIDDEN)   A = d_Xr (asel 0)
    dim3 g1(INTER / 256, CAP / 128, NEXP);
    gemm_tc<<<g1, 256, DYN_BYTES>>>(wg, INTER, HIDDEN, HIDDEN, 1, 0, 0);
    // U = x @ Wu^T
    gemm_tc<<<g1, 256, DYN_BYTES>>>(wu, INTER, HIDDEN, HIDDEN, 1, 0, 1);

    // act = tf32(silu(G) * U)
    size_t total4 = (size_t)NPAIRS * INTER / 4;
    act_kernel<<<(unsigned)((total4 + 255) / 256), 256>>>();

    // Y = act @ Wd^T  (N=HIDDEN, K=INTER)  A = d_G (asel 1)
    dim3 g3(HIDDEN / 256, CAP / 128, NEXP);
    gemm_tc<<<g3, 256, DYN_BYTES>>>(wd, HIDDEN, INTER, INTER, 0, 1, 2);

    combine_kernel<<<(T_TOKENS * HIDDEN / 4) / 256, 256>>>(out);
}

// round 11
// speedup vs baseline: 1.5968x; 1.0387x over previous
#include <cuda_runtime.h>
#include <math.h>
#include <stdint.h>

// Problem constants
#define T_TOKENS 2048
#define HIDDEN   2048
#define INTER    5632
#define NEXP     8
#define TOPK     2
#define NPAIRS   (T_TOKENS * TOPK)   // 4096
#define CAP      2048

// ---------------- device scratch ----------------
__device__ int d_cnt[NEXP];
__device__ int d_list[NEXP * CAP];
__device__ int d_eid[NPAIRS];
__device__ float d_wgt[NPAIRS];

__device__ __align__(16) float d_Xr[(size_t)T_TOKENS * HIDDEN]; // tf32-rounded x
__device__ __align__(16) float d_G[(size_t)NPAIRS * INTER];   // gate, then act (in-place)
__device__ __align__(16) float d_U[(size_t)NPAIRS * INTER];   // up
__device__ __align__(16) float d_Y[(size_t)NPAIRS * HIDDEN];  // per-pair down output

// ---------------- small kernels ----------------
__global__ void init_kernel() {
    if (threadIdx.x < NEXP) d_cnt[threadIdx.x] = 0;
}

__global__ void router_kernel(const float* __restrict__ x, const float* __restrict__ wr) {
    int warp = threadIdx.x >> 5;
    int lane = threadIdx.x & 31;
    int t = blockIdx.x * 8 + warp;
    if (t >= T_TOKENS) return;

    float acc[NEXP];
#pragma unroll
    for (int e = 0; e < NEXP; e++) acc[e] = 0.f;
    const float* xr = x + (size_t)t * HIDDEN;
    for (int j = lane; j < HIDDEN; j += 32) {
        float xv = xr[j];
#pragma unroll
        for (int e = 0; e < NEXP; e++) acc[e] += xv * wr[e * HIDDEN + j];
    }
#pragma unroll
    for (int e = 0; e < NEXP; e++) {
#pragma unroll
        for (int off = 16; off; off >>= 1)
            acc[e] += __shfl_xor_sync(0xffffffffu, acc[e], off);
    }
    if (lane == 0) {
        int e0 = 0;
#pragma unroll
        for (int e = 1; e < NEXP; e++) if (acc[e] > acc[e0]) e0 = e;
        int e1 = -1;
#pragma unroll
        for (int e = 0; e < NEXP; e++) {
            if (e == e0) continue;
            if (e1 < 0 || acc[e] > acc[e1]) e1 = e;
        }
        float v0 = acc[e0], v1 = acc[e1];
        float w1 = 1.f / (1.f + expf(v0 - v1));
        float w0 = 1.f - w1;
        d_eid[2 * t] = e0;  d_eid[2 * t + 1] = e1;
        d_wgt[2 * t] = w0;  d_wgt[2 * t + 1] = w1;
    }
}

__global__ void compact_kernel() {
    int p = blockIdx.x * blockDim.x + threadIdx.x;
    if (p >= NPAIRS) return;
    int e = d_eid[p];
    int pos = atomicAdd(&d_cnt[e], 1);
    d_list[e * CAP + pos] = p;
}

// ---------------- helpers ----------------
__device__ __forceinline__ uint32_t smem_u32(const void* p) {
    uint32_t a;
    asm("{ .reg .u64 t; cvta.to.shared.u64 t, %1; cvt.u32.u64 %0, t; }" : "=r"(a) : "l"(p));
    return a;
}
__device__ __forceinline__ uint32_t tf32r(float x) {
    uint32_t r;
    asm("cvt.rna.tf32.f32 %0, %1;" : "=r"(r) : "f"(x));
    return r;
}
__device__ __forceinline__ float tf32rf(float x) {
    uint32_t r = tf32r(x);
    return __uint_as_float(r);
}
__device__ __forceinline__ void mma_tf32(float* c, const uint32_t* a, const uint32_t* b) {
    asm volatile("mma.sync.aligned.m16n8k8.row.col.f32.tf32.tf32.f32 "
                 "{%0,%1,%2,%3}, {%4,%5,%6,%7}, {%8,%9}, {%0,%1,%2,%3};"
                 : "+f"(c[0]), "+f"(c[1]), "+f"(c[2]), "+f"(c[3])
                 : "r"(a[0]), "r"(a[1]), "r"(a[2]), "r"(a[3]),
                   "r"(b[0]), "r"(b[1]));
}
__device__ __forceinline__ void ldm4(uint32_t* d, uint32_t addr) {
    asm volatile("ldmatrix.sync.aligned.m8n8.x4.shared.b16 {%0,%1,%2,%3}, [%4];"
                 : "=r"(d[0]), "=r"(d[1]), "=r"(d[2]), "=r"(d[3]) : "r"(addr));
}
__device__ __forceinline__ void cp16(uint32_t smem_dst, const void* gptr) {
    asm volatile("cp.async.cg.shared.global [%0], [%1], 16;" :: "r"(smem_dst), "l"(gptr));
}

// ---------------- expert-grouped tf32 tensor GEMM (ldmatrix, 2 CTA/SM) ----------------
// C[pid][n] = sum_k A[pid>>shift][k] * B_e[n][k]
// Tile: BM=128, BN=128, BK=32. 256 threads, 8 warps in 2(m) x 4(n), warp tile 64x32.
// A source selected IN KERNEL: asel 0 -> d_Xr, 1 -> d_G. B cvt'd on fragments post-ldmatrix.
#define BK 32
#define SMS 36                                 // padded smem row stride (floats); 144B
#define STAGE_F ((128 + 128) * SMS)            // floats per stage
#define NSTAGE 2

__global__ __launch_bounds__(256, 2)
void gemm_tc(const float* __restrict__ Ball,
             int N, int K, int lda, int shift, int asel, int csel)
{
    int e = blockIdx.z;
    int n_e = d_cnt[e];
    int mbase = blockIdx.y * 128;
    if (mbase >= n_e) return;
    int nbase = blockIdx.x * 128;

    const float* A = asel ? d_G : d_Xr;
    float* C = (csel == 0) ? d_G : (csel == 1) ? d_U : d_Y;
    const float* B = Ball + (size_t)e * N * K;

    extern __shared__ float sm[];
    int* s_pid = (int*)(sm + NSTAGE * STAGE_F);
    uint32_t smbase = smem_u32(sm);

    int tid = threadIdx.x;
    int lane = tid & 31;
    int wid = tid >> 5;
    int wm = wid & 1;          // 0..1  (64 rows)
    int wn = wid >> 1;         // 0..3  (32 cols)

    if (tid < 128) {
        int lp = mbase + tid;
        s_pid[tid] = d_list[e * CAP + (lp < n_e ? lp : mbase)];
    }
    __syncthreads();

    // loader mapping: 4 chunks/thread per operand; chunk = (row, 16B of k)
    const char* aG[4];
    const char* bG[4];
    uint32_t aS[4], bS[4];
#pragma unroll
    for (int i = 0; i < 4; i++) {
        int idx = tid + i * 256;          // 0..1023
        int row = idx >> 3;
        int c4  = (idx & 7) * 4;
        aG[i] = (const char*)(A + (size_t)(s_pid[row] >> shift) * lda + c4);
        aS[i] = (uint32_t)((row * SMS + c4) * 4);
        bG[i] = (const char*)(B + (size_t)(nbase + row) * K + c4);
        bS[i] = (uint32_t)((128 * SMS + row * SMS + c4) * 4);
    }

    int KT = K / BK;

    auto issue = [&](int st, int kb) {
        uint32_t sb = smbase + (uint32_t)(st * STAGE_F * 4);
        size_t go = (size_t)kb * BK * 4;
#pragma unroll
        for (int i = 0; i < 4; i++) cp16(sb + aS[i], aG[i] + go);
#pragma unroll
        for (int i = 0; i < 4; i++) cp16(sb + bS[i], bG[i] + go);
        asm volatile("cp.async.commit_group;" ::: "memory");
    };

    issue(0, 0);
    issue(1, 1);

    float acc[4][4][4];
#pragma unroll
    for (int mt = 0; mt < 4; mt++)
#pragma unroll
        for (int nt = 0; nt < 4; nt++)
#pragma unroll
            for (int q = 0; q < 4; q++) acc[mt][nt][q] = 0.f;

    // ldmatrix per-lane addresses (byte offsets within a stage)
    int lg = lane >> 3, lr = lane & 7;
    // A mt tile: matrices g0=(r0-7,k0-3) g1=(r8-15,k0-3) g2=(r0-7,k4-7) g3=(r8-15,k4-7)
    uint32_t aoff[4];
#pragma unroll
    for (int mt = 0; mt < 4; mt++) {
        int row = wm * 64 + mt * 16 + ((lg & 1) << 3) + lr;
        int col = (lg >> 1) << 2;
        aoff[mt] = (uint32_t)((row * SMS + col) * 4);
    }
    // B ntp tile (16 n-rows each): g0=(n0-7,k0-3) g1=(n0-7,k4-7) g2=(n8-15,k0-3) g3=(n8-15,k4-7)
    uint32_t boff[2];
#pragma unroll
    for (int ntp = 0; ntp < 2; ntp++) {
        int row = 128 + wn * 32 + ntp * 16 + ((lg >> 1) << 3) + lr;
        int col = (lg & 1) << 2;
        boff[ntp] = (uint32_t)((row * SMS + col) * 4);
    }

    for (int kb = 0; kb < KT; kb++) {
        int st = kb & 1;
        if (kb + 1 < KT) {
            asm volatile("cp.async.wait_group 1;" ::: "memory");
        } else {
            asm volatile("cp.async.wait_group 0;" ::: "memory");
        }
        __syncthreads();                           // stage kb visible

        uint32_t sb32 = smbase + (uint32_t)(st * STAGE_F * 4);
#pragma unroll
        for (int ks = 0; ks < 4; ks++) {
            uint32_t kbyte = (uint32_t)(ks * 32);  // 8 floats
            uint32_t af[4][4];
            uint32_t bfr[2][4];
#pragma unroll
            for (int mt = 0; mt < 4; mt++) ldm4(af[mt], sb32 + aoff[mt] + kbyte);
#pragma unroll
            for (int ntp = 0; ntp < 2; ntp++) ldm4(bfr[ntp], sb32 + boff[ntp] + kbyte);
            // round B fragments (A is pre-rounded)
#pragma unroll
            for (int ntp = 0; ntp < 2; ntp++)
#pragma unroll
                for (int q = 0; q < 4; q++)
                    bfr[ntp][q] = tf32r(__uint_as_float(bfr[ntp][q]));
#pragma unroll
            for (int mt = 0; mt < 4; mt++)
#pragma unroll
                for (int ntp = 0; ntp < 2; ntp++) {
                    mma_tf32(acc[mt][2 * ntp],     af[mt], &bfr[ntp][0]);
                    mma_tf32(acc[mt][2 * ntp + 1], af[mt], &bfr[ntp][2]);
                }
        }
        __syncthreads();                           // stage kb fully consumed
        if (kb + 2 < KT) issue(st, kb + 2);
    }

    // ---- epilogue: scatter accum rows via pid list ----
    int gid = lane >> 2;
    int tig = lane & 3;
#pragma unroll
    for (int mt = 0; mt < 4; mt++) {
        int mrow0 = wm * 64 + mt * 16 + gid;
        int mrow1 = mrow0 + 8;
        bool v0 = (mbase + mrow0) < n_e;
        bool v1 = (mbase + mrow1) < n_e;
        float* c0 = v0 ? (C + (size_t)s_pid[mrow0] * N + nbase + wn * 32 + tig * 2) : (float*)0;
        float* c1 = v1 ? (C + (size_t)s_pid[mrow1] * N + nbase + wn * 32 + tig * 2) : (float*)0;
#pragma unroll
        for (int nt = 0; nt < 4; nt++) {
            if (v0) *(float2*)(c0 + nt * 8) = make_float2(acc[mt][nt][0], acc[mt][nt][1]);
            if (v1) *(float2*)(c1 + nt * 8) = make_float2(acc[mt][nt][2], acc[mt][nt][3]);
        }
    }
}

#define DYN_BYTES (NSTAGE * STAGE_F * 4 + 128 * 4 + 16)

// ---------------- elementwise ----------------
__global__ void roundx_kernel(const float* __restrict__ x) {
    int i = blockIdx.x * blockDim.x + threadIdx.x;
    if (i >= T_TOKENS * HIDDEN / 4) return;
    float4 v = ((const float4*)x)[i];
    float4 o;
    o.x = tf32rf(v.x); o.y = tf32rf(v.y); o.z = tf32rf(v.z); o.w = tf32rf(v.w);
    ((float4*)d_Xr)[i] = o;
}

// act = tf32_round(silu(G) * U), written in place into G
__global__ void act_kernel() {
    size_t i = (size_t)blockIdx.x * blockDim.x + threadIdx.x;
    if (i >= (size_t)NPAIRS * INTER / 4) return;
    float4 g = ((const float4*)d_G)[i];
    float4 u = ((const float4*)d_U)[i];
    float4 o;
    o.x = tf32rf(g.x / (1.f + expf(-g.x)) * u.x);
    o.y = tf32rf(g.y / (1.f + expf(-g.y)) * u.y);
    o.z = tf32rf(g.z / (1.f + expf(-g.z)) * u.z);
    o.w = tf32rf(g.w / (1.f + expf(-g.w)) * u.w);
    ((float4*)d_G)[i] = o;
}

__global__ void combine_kernel(float* __restrict__ out) {
    int idx = blockIdx.x * blockDim.x + threadIdx.x;
    if (idx >= T_TOKENS * HIDDEN / 4) return;
    int t = idx / (HIDDEN / 4);
    int h4 = idx % (HIDDEN / 4);
    float w0 = d_wgt[2 * t], w1 = d_wgt[2 * t + 1];
    float4 a = ((const float4*)d_Y)[(size_t)(2 * t) * (HIDDEN / 4) + h4];
    float4 b = ((const float4*)d_Y)[(size_t)(2 * t + 1) * (HIDDEN / 4) + h4];
    float4 o;
    o.x = w0 * a.x + w1 * b.x;
    o.y = w0 * a.y + w1 * b.y;
    o.z = w0 * a.z + w1 * b.z;
    o.w = w0 * a.w + w1 * b.w;
    ((float4*)out)[idx] = o;
}

// ---------------- launch ----------------
extern "C" void kernel_launch(void* const* d_in, const int* in_sizes, int n_in,
                              void* d_out, int out_size) {
    const float* x  = (const float*)d_in[0];
    const float* wr = (const float*)d_in[1];
    const float* wg = (const float*)d_in[2];
    const float* wu = (const float*)d_in[3];
    const float* wd = (const float*)d_in[4];
    float* out = (float*)d_out;

    cudaFuncSetAttribute(gemm_tc, cudaFuncAttributeMaxDynamicSharedMemorySize, DYN_BYTES);

    init_kernel<<<1, 32>>>();
    router_kernel<<<T_TOKENS / 8, 256>>>(x, wr);
    compact_kernel<<<NPAIRS / 256, 256>>>();
    roundx_kernel<<<(T_TOKENS * HIDDEN / 4) / 256, 256>>>(x);

    // G = x @ Wg^T   (N=INTER, K=HIDDEN)   A = d_Xr (asel 0)
    dim3 g1(INTER / 128, CAP / 128, NEXP);
    gemm_tc<<<g1, 256, DYN_BYTES>>>(wg, INTER, HIDDEN, HIDDEN, 1, 0, 0);
    // U = x @ Wu^T
    gemm_tc<<<g1, 256, DYN_BYTES>>>(wu, INTER, HIDDEN, HIDDEN, 1, 0, 1);

    // act = tf32(silu(G) * U)
    size_t total4 = (size_t)NPAIRS * INTER / 4;
    act_kernel<<<(unsigned)((total4 + 255) / 256), 256>>>();

    // Y = act @ Wd^T  (N=HIDDEN, K=INTER)  A = d_G (asel 1)
    dim3 g3(HIDDEN / 128, CAP / 128, NEXP);
    gemm_tc<<<g3, 256, DYN_BYTES>>>(wd, HIDDEN, INTER, INTER, 0, 1, 2);

    combine_kernel<<<(T_TOKENS * HIDDEN / 4) / 256, 256>>>(out);
}

// round 12
// speedup vs baseline: 1.7929x; 1.1228x over previous
#include <cuda_runtime.h>
#include <cuda_fp16.h>
#include <math.h>
#include <stdint.h>

// Problem constants
#define T_TOKENS 2048
#define HIDDEN   2048
#define INTER    5632
#define NEXP     8
#define TOPK     2
#define NPAIRS   (T_TOKENS * TOPK)   // 4096
#define CAP      2048

// ---------------- device scratch ----------------
__device__ int d_cnt[NEXP];
__device__ int d_list[NEXP * CAP];
__device__ int d_eid[NPAIRS];
__device__ float d_wgt[NPAIRS];

__device__ __align__(16) float d_G[(size_t)NPAIRS * INTER];   // gate, then act (in-place)
__device__ __align__(16) float d_U[(size_t)NPAIRS * INTER];   // up
__device__ __align__(16) float d_Y[(size_t)NPAIRS * HIDDEN];  // per-pair down output

// ---------------- small kernels ----------------
__global__ void init_kernel() {
    if (threadIdx.x < NEXP) d_cnt[threadIdx.x] = 0;
}

__global__ void router_kernel(const float* __restrict__ x, const float* __restrict__ wr) {
    int warp = threadIdx.x >> 5;
    int lane = threadIdx.x & 31;
    int t = blockIdx.x * 8 + warp;
    if (t >= T_TOKENS) return;

    float acc[NEXP];
#pragma unroll
    for (int e = 0; e < NEXP; e++) acc[e] = 0.f;
    const float* xr = x + (size_t)t * HIDDEN;
    for (int j = lane; j < HIDDEN; j += 32) {
        float xv = xr[j];
#pragma unroll
        for (int e = 0; e < NEXP; e++) acc[e] += xv * wr[e * HIDDEN + j];
    }
#pragma unroll
    for (int e = 0; e < NEXP; e++) {
#pragma unroll
        for (int off = 16; off; off >>= 1)
            acc[e] += __shfl_xor_sync(0xffffffffu, acc[e], off);
    }
    if (lane == 0) {
        int e0 = 0;
#pragma unroll
        for (int e = 1; e < NEXP; e++) if (acc[e] > acc[e0]) e0 = e;
        int e1 = -1;
#pragma unroll
        for (int e = 0; e < NEXP; e++) {
            if (e == e0) continue;
            if (e1 < 0 || acc[e] > acc[e1]) e1 = e;
        }
        float v0 = acc[e0], v1 = acc[e1];
        float w1 = 1.f / (1.f + expf(v0 - v1));
        float w0 = 1.f - w1;
        d_eid[2 * t] = e0;  d_eid[2 * t + 1] = e1;
        d_wgt[2 * t] = w0;  d_wgt[2 * t + 1] = w1;
    }
}

__global__ void compact_kernel() {
    int p = blockIdx.x * blockDim.x + threadIdx.x;
    if (p >= NPAIRS) return;
    int e = d_eid[p];
    int pos = atomicAdd(&d_cnt[e], 1);
    d_list[e * CAP + pos] = p;
}

// ---------------- helpers ----------------
__device__ __forceinline__ uint32_t smem_u32(const void* p) {
    uint32_t a;
    asm("{ .reg .u64 t; cvta.to.shared.u64 t, %1; cvt.u32.u64 %0, t; }" : "=r"(a) : "l"(p));
    return a;
}
// pack two f32 into f16x2: lo half = a, hi half = b
__device__ __forceinline__ uint32_t packf16(float a, float b) {
    uint32_t d;
    asm("cvt.rn.f16x2.f32 %0, %1, %2;" : "=r"(d) : "f"(b), "f"(a));
    return d;
}
__device__ __forceinline__ void mma_f16(float* c, const uint32_t* a, const uint32_t* b) {
    asm volatile("mma.sync.aligned.m16n8k16.row.col.f32.f16.f16.f32 "
                 "{%0,%1,%2,%3}, {%4,%5,%6,%7}, {%8,%9}, {%0,%1,%2,%3};"
                 : "+f"(c[0]), "+f"(c[1]), "+f"(c[2]), "+f"(c[3])
                 : "r"(a[0]), "r"(a[1]), "r"(a[2]), "r"(a[3]),
                   "r"(b[0]), "r"(b[1]));
}
__device__ __forceinline__ void ldm4(uint32_t* d, uint32_t addr) {
    asm volatile("ldmatrix.sync.aligned.m8n8.x4.shared.b16 {%0,%1,%2,%3}, [%4];"
                 : "=r"(d[0]), "=r"(d[1]), "=r"(d[2]), "=r"(d[3]) : "r"(addr));
}
__device__ __forceinline__ void cp16(uint32_t smem_dst, const void* gptr) {
    asm volatile("cp.async.cg.shared.global [%0], [%1], 16;" :: "r"(smem_dst), "l"(gptr));
}

// ---------------- expert-grouped fp16 tensor GEMM ----------------
// C[pid][n] = sum_k A[pid>>shift][k] * B_e[n][k]
// Tile: BM=128, BN=256, BK=32. 256 threads, 8 warps in 2(m) x 4(n), warp tile 64x64.
// fp32 staged via cp.async (2 stages), converted in smem to fp16, ldmatrix b16 + m16n8k16.
#define BK 32
#define SMS 36                                  // fp32 staging row stride (floats)
#define STAGE_F ((128 + 256) * SMS)             // fp32 floats per stage
#define NSTAGE 2
#define RS2B 80                                 // fp16 tile row stride in BYTES (32 halfs + pad)
#define H16B (NSTAGE * STAGE_F * 4)             // byte offset of fp16 tile buffer
#define H16SZ (384 * RS2B)                      // fp16 tile bytes
#define PIDOFF (H16B + H16SZ)
#define DYN_BYTES (PIDOFF + 128 * 4 + 16)

__global__ __launch_bounds__(256, 1)
void gemm_tc(const float* __restrict__ Aext, const float* __restrict__ Ball,
             int N, int K, int lda, int shift, int asel, int csel)
{
    int e = blockIdx.z;
    int n_e = d_cnt[e];
    int mbase = blockIdx.y * 128;
    if (mbase >= n_e) return;
    int nbase = blockIdx.x * 256;

    const float* A = asel ? d_G : Aext;
    float* C = (csel == 0) ? d_G : (csel == 1) ? d_U : d_Y;
    const float* B = Ball + (size_t)e * N * K;

    extern __shared__ float sm[];
    int* s_pid = (int*)((char*)sm + PIDOFF);
    uint32_t smbase = smem_u32(sm);

    int tid = threadIdx.x;
    int lane = tid & 31;
    int wid = tid >> 5;
    int wm = wid & 1;          // 0..1  (64 rows)
    int wn = wid >> 1;         // 0..3  (64 cols)

    if (tid < 128) {
        int lp = mbase + tid;
        s_pid[tid] = d_list[e * CAP + (lp < n_e ? lp : mbase)];
    }
    __syncthreads();

    // loader mapping: A 4 chunks/thread, B 8 chunks/thread; chunk = (row, 16B of k)
    const char* aG[4];
    const char* bG[8];
    uint32_t aS[4], bS[8];
#pragma unroll
    for (int i = 0; i < 4; i++) {
        int idx = tid + i * 256;          // 0..1023
        int row = idx >> 3;
        int c4  = (idx & 7) * 4;
        aG[i] = (const char*)(A + (size_t)(s_pid[row] >> shift) * lda + c4);
        aS[i] = (uint32_t)((row * SMS + c4) * 4);
    }
#pragma unroll
    for (int i = 0; i < 8; i++) {
        int idx = tid + i * 256;          // 0..2047
        int row = idx >> 3;
        int c4  = (idx & 7) * 4;
        bG[i] = (const char*)(B + (size_t)(nbase + row) * K + c4);
        bS[i] = (uint32_t)((128 * SMS + row * SMS + c4) * 4);
    }

    int KT = K / BK;

    auto issue = [&](int st, int kb) {
        uint32_t sb = smbase + (uint32_t)(st * STAGE_F * 4);
        size_t go = (size_t)kb * BK * 4;
#pragma unroll
        for (int i = 0; i < 4; i++) cp16(sb + aS[i], aG[i] + go);
#pragma unroll
        for (int i = 0; i < 8; i++) cp16(sb + bS[i], bG[i] + go);
        asm volatile("cp.async.commit_group;" ::: "memory");
    };

    issue(0, 0);
    issue(1, 1);

    float acc[4][8][4];
#pragma unroll
    for (int mt = 0; mt < 4; mt++)
#pragma unroll
        for (int nt = 0; nt < 8; nt++)
#pragma unroll
            for (int q = 0; q < 4; q++) acc[mt][nt][q] = 0.f;

    // ---- ldmatrix per-lane addresses in the fp16 tile (byte offsets from smbase) ----
    int lg = lane >> 3, lr = lane & 7;
    // A mt tile: g0=(r0-7,k0-7) g1=(r8-15,k0-7) g2=(r0-7,k8-15) g3=(r8-15,k8-15)
    uint32_t aoff[4];
#pragma unroll
    for (int mt = 0; mt < 4; mt++) {
        int row = wm * 64 + mt * 16 + ((lg & 1) << 3) + lr;
        aoff[mt] = (uint32_t)(H16B + row * RS2B + ((lg >> 1) << 4));
    }
    // B ntp tile: g0=(n0-7,k0-7) g1=(n0-7,k8-15) g2=(n8-15,k0-7) g3=(n8-15,k8-15)
    uint32_t boff[4];
#pragma unroll
    for (int ntp = 0; ntp < 4; ntp++) {
        int row = 128 + wn * 64 + ntp * 16 + ((lg >> 1) << 3) + lr;
        boff[ntp] = (uint32_t)(H16B + row * RS2B + ((lg & 1) << 4));
    }

    char* h16 = (char*)sm + H16B;

    for (int kb = 0; kb < KT; kb++) {
        int st = kb & 1;
        if (kb + 1 < KT) {
            asm volatile("cp.async.wait_group 1;" ::: "memory");
        } else {
            asm volatile("cp.async.wait_group 0;" ::: "memory");
        }
        __syncthreads();                           // stage kb visible; prev MMA phase done

        // ---- convert fp32 staging -> fp16 tile (rows tid, and 256+tid for tid<128) ----
        {
            const float* stg = sm + st * STAGE_F;
#pragma unroll
            for (int h = 0; h < 2; h++) {
                int r = tid + h * 256;
                if (h == 0 || tid < 128) {
                    const float* src = stg + r * SMS;
                    uint32_t* dst = (uint32_t*)(h16 + r * RS2B);
                    uint32_t pk[16];
#pragma unroll
                    for (int j = 0; j < 8; j++) {
                        float4 v = *(const float4*)(src + j * 4);
                        pk[j * 2]     = packf16(v.x, v.y);
                        pk[j * 2 + 1] = packf16(v.z, v.w);
                    }
#pragma unroll
                    for (int j = 0; j < 4; j++)
                        *(uint4*)(dst + j * 4) = make_uint4(pk[j*4], pk[j*4+1], pk[j*4+2], pk[j*4+3]);
                }
            }
        }
        __syncthreads();                           // fp16 tile ready; staging slot free
        if (kb + 2 < KT) issue(st, kb + 2);

        // ---- MMA phase: 2 k16 steps ----
#pragma unroll
        for (int ks = 0; ks < 2; ks++) {
            uint32_t kbyte = (uint32_t)(ks * 32);  // 16 halfs
            uint32_t af[4][4], bf[4][4];
#pragma unroll
            for (int mt = 0; mt < 4; mt++) ldm4(af[mt], smbase + aoff[mt] + kbyte);
#pragma unroll
            for (int ntp = 0; ntp < 4; ntp++) ldm4(bf[ntp], smbase + boff[ntp] + kbyte);
#pragma unroll
            for (int mt = 0; mt < 4; mt++)
#pragma unroll
                for (int ntp = 0; ntp < 4; ntp++) {
                    mma_f16(acc[mt][2 * ntp],     af[mt], &bf[ntp][0]);
                    mma_f16(acc[mt][2 * ntp + 1], af[mt], &bf[ntp][2]);
                }
        }
    }

    // ---- epilogue: scatter accum rows via pid list ----
    int gid = lane >> 2;
    int tig = lane & 3;
#pragma unroll
    for (int mt = 0; mt < 4; mt++) {
        int mrow0 = wm * 64 + mt * 16 + gid;
        int mrow1 = mrow0 + 8;
        bool v0 = (mbase + mrow0) < n_e;
        bool v1 = (mbase + mrow1) < n_e;
        float* c0 = v0 ? (C + (size_t)s_pid[mrow0] * N + nbase + wn * 64 + tig * 2) : (float*)0;
        float* c1 = v1 ? (C + (size_t)s_pid[mrow1] * N + nbase + wn * 64 + tig * 2) : (float*)0;
#pragma unroll
        for (int nt = 0; nt < 8; nt++) {
            if (v0) *(float2*)(c0 + nt * 8) = make_float2(acc[mt][nt][0], acc[mt][nt][1]);
            if (v1) *(float2*)(c1 + nt * 8) = make_float2(acc[mt][nt][2], acc[mt][nt][3]);
        }
    }
}

// ---------------- elementwise ----------------
// act = silu(G) * U, written in place into G (fp32; GEMM3 converts to fp16 at staging)
__global__ void act_kernel() {
    size_t i = (size_t)blockIdx.x * blockDim.x + threadIdx.x;
    if (i >= (size_t)NPAIRS * INTER / 4) return;
    float4 g = ((const float4*)d_G)[i];
    float4 u = ((const float4*)d_U)[i];
    float4 o;
    o.x = g.x / (1.f + expf(-g.x)) * u.x;
    o.y = g.y / (1.f + expf(-g.y)) * u.y;
    o.z = g.z / (1.f + expf(-g.z)) * u.z;
    o.w = g.w / (1.f + expf(-g.w)) * u.w;
    ((float4*)d_G)[i] = o;
}

__global__ void combine_kernel(float* __restrict__ out) {
    int idx = blockIdx.x * blockDim.x + threadIdx.x;
    if (idx >= T_TOKENS * HIDDEN / 4) return;
    int t = idx / (HIDDEN / 4);
    int h4 = idx % (HIDDEN / 4);
    float w0 = d_wgt[2 * t], w1 = d_wgt[2 * t + 1];
    float4 a = ((const float4*)d_Y)[(size_t)(2 * t) * (HIDDEN / 4) + h4];
    float4 b = ((const float4*)d_Y)[(size_t)(2 * t + 1) * (HIDDEN / 4) + h4];
    float4 o;
    o.x = w0 * a.x + w1 * b.x;
    o.y = w0 * a.y + w1 * b.y;
    o.z = w0 * a.z + w1 * b.z;
    o.w = w0 * a.w + w1 * b.w;
    ((float4*)out)[idx] = o;
}

// ---------------- launch ----------------
extern "C" void kernel_launch(void* const* d_in, const int* in_sizes, int n_in,
                              void* d_out, int out_size) {
    const float* x  = (const float*)d_in[0];
    const float* wr = (const float*)d_in[1];
    const float* wg = (const float*)d_in[2];
    const float* wu = (const float*)d_in[3];
    const float* wd = (const float*)d_in[4];
    float* out = (float*)d_out;

    cudaFuncSetAttribute(gemm_tc, cudaFuncAttributeMaxDynamicSharedMemorySize, DYN_BYTES);

    init_kernel<<<1, 32>>>();
    router_kernel<<<T_TOKENS / 8, 256>>>(x, wr);
    compact_kernel<<<NPAIRS / 256, 256>>>();

    // G = x @ Wg^T   (N=INTER, K=HIDDEN)
    dim3 g1(INTER / 256, CAP / 128, NEXP);
    gemm_tc<<<g1, 256, DYN_BYTES>>>(x, wg, INTER, HIDDEN, HIDDEN, 1, 0, 0);
    // U = x @ Wu^T
    gemm_tc<<<g1, 256, DYN_BYTES>>>(x, wu, INTER, HIDDEN, HIDDEN, 1, 0, 1);

    // act = silu(G) * U
    size_t total4 = (size_t)NPAIRS * INTER / 4;
    act_kernel<<<(unsigned)((total4 + 255) / 256), 256>>>();

    // Y = act @ Wd^T  (N=HIDDEN, K=INTER)
    dim3 g3(HIDDEN / 256, CAP / 128, NEXP);
    gemm_tc<<<g3, 256, DYN_BYTES>>>(nullptr, wd, HIDDEN, INTER, INTER, 0, 1, 2);

    combine_kernel<<<(T_TOKENS * HIDDEN / 4) / 256, 256>>>(out);
}